// round 6
// baseline (speedup 1.0000x reference)
#include <cuda_runtime.h>

// Problem shapes
#define B_ 128
#define S_ 37
#define T_ 2048
#define D_ 256
#define ST_ 8
#define C_ 2
#define MERGED_ 264
#define NF (2*S_)          // 74 features (x ++ mask)
#define TC 128             // time chunk per CTA
#define NCHUNK (T_/TC)     // 16

#define G2A 8              // batches per CTA in stage2a (16 CTAs)
#define G2B 4              // batches per CTA in stage2b (32 CTAs)

// Per-chunk partial reductions (written without atomics -> deterministic)
__device__ float g_px[(size_t)NCHUNK * B_ * NF];
__device__ float g_pm[NCHUNK * B_];
__device__ float g_pt[NCHUNK * B_];
__device__ __align__(16) float g_comb[B_ * MERGED_];   // [b][264]

__device__ __forceinline__ float wred(float v) {
#pragma unroll
    for (int o = 16; o > 0; o >>= 1) v += __shfl_xor_sync(0xffffffffu, v, o);
    return v;
}

// ---------------------------------------------------------------------------
// Stage 1: HBM/L2-roofline pass over x + sensor_mask (77.6 MB).
// ---------------------------------------------------------------------------
__global__ __launch_bounds__(256) void stage1(const float* __restrict__ x,
                                              const int*   __restrict__ smk,
                                              const float* __restrict__ tm) {
    __shared__ float xs[S_ * TC];
    __shared__ float ms[S_ * TC];
    __shared__ float valid[TC];
    __shared__ float red[8][2];

    const int chunk = blockIdx.x;
    const int b     = blockIdx.y;
    const int t0    = chunk * TC;

    const float* xb = x   + (size_t)b * S_ * T_ + t0;
    const int*   mb = smk + (size_t)b * S_ * T_ + t0;

    for (int idx = threadIdx.x; idx < S_ * (TC / 4); idx += 256) {
        int s = idx / (TC / 4);
        int j = (idx % (TC / 4)) * 4;
        float4 v = *(const float4*)(xb + (size_t)s * T_ + j);
        *(float4*)(xs + s * TC + j) = v;
        int4 m = *(const int4*)(mb + (size_t)s * T_ + j);
        *(float4*)(ms + s * TC + j) =
            make_float4((float)m.x, (float)m.y, (float)m.z, (float)m.w);
    }
    __syncthreads();

    float vf = 0.f, tv = 0.f;
    if (threadIdx.x < TC) {
        const int t = threadIdx.x;
        int nz = 0;
#pragma unroll
        for (int s = 0; s < S_; s++) {
            nz |= (xs[s * TC + t] != 0.f);
            nz |= (ms[s * TC + t] != 0.f);
        }
        vf = nz ? 1.f : 0.f;
        valid[t] = vf;
        tv = vf * tm[(size_t)b * T_ + t0 + t];
    }

    const int w = threadIdx.x >> 5, lane = threadIdx.x & 31;
    float rv = wred(vf), rt = wred(tv);
    if (lane == 0) { red[w][0] = rv; red[w][1] = rt; }
    __syncthreads();   // also makes valid[] visible to all warps
    if (threadIdx.x == 0) {
        float a = 0.f, c = 0.f;
#pragma unroll
        for (int i = 0; i < 8; i++) { a += red[i][0]; c += red[i][1]; }
        g_pm[chunk * B_ + b] = a;
        g_pt[chunk * B_ + b] = c;
    }

    for (int f = w; f < NF; f += 8) {
        const float* src = (f < S_) ? (xs + f * TC) : (ms + (f - S_) * TC);
        float p = 0.f;
#pragma unroll
        for (int j = lane; j < TC; j += 32) p += valid[j] * src[j];
        p = wred(p);
        if (lane == 0) g_px[((size_t)chunk * B_ + b) * NF + f] = p;
    }
}

// ---------------------------------------------------------------------------
// Stage 2a: pooled projection + static embed for G2A batches per CTA.
// Thread tid<256 owns dim tid; Ws reads are warp-coalesced and amortized
// over G2A batches with independent accumulators.
// ---------------------------------------------------------------------------
__global__ __launch_bounds__(264) void stage2a(
    const float* __restrict__ stat,
    const float* __restrict__ Ws,  const float* __restrict__ bs,
    const float* __restrict__ Wt,  const float* __restrict__ bt,
    const float* __restrict__ Wst, const float* __restrict__ bst) {
    __shared__ float xsum[NF][G2A];     // k-major for broadcast-friendly reads
    __shared__ float den_s[G2A], tsc_s[G2A];

    const int b0  = blockIdx.x * G2A;
    const int tid = threadIdx.x;

    // Reduce per-chunk partials for all G2A batches.
    for (int idx = tid; idx < G2A * NF; idx += 264) {
        const int g = idx / NF, f = idx % NF;
        float a = 0.f;
#pragma unroll
        for (int c = 0; c < NCHUNK; c++)
            a += g_px[((size_t)c * B_ + (b0 + g)) * NF + f];
        xsum[f][g] = a;
    }
    if (tid < G2A) {
        float a = 0.f, t = 0.f;
#pragma unroll
        for (int c = 0; c < NCHUNK; c++) {
            a += g_pm[c * B_ + b0 + tid];
            t += g_pt[c * B_ + b0 + tid];
        }
        float den = fmaxf(a, 1e-9f);
        den_s[tid] = den;
        tsc_s[tid] = t / den;
    }
    __syncthreads();

    if (tid < D_) {
        float acc[G2A];
#pragma unroll
        for (int g = 0; g < G2A; g++) acc[g] = 0.f;
#pragma unroll 8
        for (int k = 0; k < NF; k++) {
            const float w = Ws[k * D_ + tid];   // coalesced across warp
#pragma unroll
            for (int g = 0; g < G2A; g++) acc[g] += xsum[k][g] * w;
        }
        const float bias = bs[tid] + bt[tid];
        const float wt   = Wt[tid];
#pragma unroll
        for (int g = 0; g < G2A; g++)
            g_comb[(b0 + g) * MERGED_ + tid] =
                acc[g] / den_s[g] + bias + tsc_s[g] * wt;
    } else {
        // static embedding: 8 dims x G2A batches on the spare 8 threads
        const int j = tid - D_;
        for (int g = 0; g < G2A; g++) {
            float p = bst[j];
#pragma unroll
            for (int i = 0; i < ST_; i++)
                p += stat[(b0 + g) * ST_ + i] * Wst[i * ST_ + j];
            g_comb[(b0 + g) * MERGED_ + D_ + j] = p;
        }
    }
}

// ---------------------------------------------------------------------------
// Stage 2b: merge GEMM (relu(comb @ Wm + bm)) for G2B batches per CTA,
// then the classifier. Thread tid owns output column tid; Wm reads are
// warp-coalesced, comb comes from smem float4 broadcasts (4 batches/LDS).
// ---------------------------------------------------------------------------
__global__ __launch_bounds__(288) void stage2b(
    const float* __restrict__ Wm,  const float* __restrict__ bm,
    const float* __restrict__ Wc,  const float* __restrict__ bc,
    float* __restrict__ out) {
    __shared__ __align__(16) float combT[MERGED_][G2B];   // [k][g]
    __shared__ float comb2[G2B][MERGED_];

    const int b0  = blockIdx.x * G2B;
    const int tid = threadIdx.x;

    // Load comb rows for the G2B batches, store k-major.
    for (int idx = tid; idx < G2B * MERGED_; idx += 288) {
        const int g = idx / MERGED_, k = idx % MERGED_;
        combT[k][g] = g_comb[(b0 + g) * MERGED_ + k];
    }
    __syncthreads();

    if (tid < MERGED_) {
        float a0 = 0.f, a1 = 0.f, a2 = 0.f, a3 = 0.f;
#pragma unroll 8
        for (int k = 0; k < MERGED_; k++) {
            const float w = Wm[k * MERGED_ + tid];     // coalesced
            const float4 c4 = *(const float4*)&combT[k][0];  // broadcast
            a0 += c4.x * w; a1 += c4.y * w; a2 += c4.z * w; a3 += c4.w * w;
        }
        const float bias = bm[tid];
        comb2[0][tid] = fmaxf(a0 + bias, 0.f);
        comb2[1][tid] = fmaxf(a1 + bias, 0.f);
        comb2[2][tid] = fmaxf(a2 + bias, 0.f);
        comb2[3][tid] = fmaxf(a3 + bias, 0.f);
    }
    __syncthreads();

    // Classifier: 8 (g,c) pairs, one warp each (warps 0..7 of 9).
    const int w = tid >> 5, lane = tid & 31;
    if (w < G2B * C_) {
        const int g = w >> 1, c = w & 1;
        float p = 0.f;
#pragma unroll
        for (int i = lane; i < MERGED_; i += 32) p += comb2[g][i] * Wc[i * C_ + c];
        p = wred(p);
        if (lane == 0) out[(b0 + g) * C_ + c] = p + bc[c];
    }
}

extern "C" void kernel_launch(void* const* d_in, const int* in_sizes, int n_in,
                              void* d_out, int out_size) {
    const float* x   = (const float*)d_in[0];
    const float* st  = (const float*)d_in[1];
    const float* tm  = (const float*)d_in[2];
    const int*   smk = (const int*)  d_in[3];
    const float* Ws  = (const float*)d_in[4];
    const float* bs  = (const float*)d_in[5];
    const float* Wt  = (const float*)d_in[6];
    const float* bt  = (const float*)d_in[7];
    const float* Wst = (const float*)d_in[8];
    const float* bst = (const float*)d_in[9];
    const float* Wm  = (const float*)d_in[10];
    const float* bm  = (const float*)d_in[11];
    const float* Wc  = (const float*)d_in[12];
    const float* bc  = (const float*)d_in[13];

    stage1<<<dim3(NCHUNK, B_), 256>>>(x, smk, tm);
    stage2a<<<B_ / G2A, 264>>>(st, Ws, bs, Wt, bt, Wst, bst);
    stage2b<<<B_ / G2B, 288>>>(Wm, bm, Wc, bc, (float*)d_out);
}

// round 7
// speedup vs baseline: 1.1837x; 1.1837x over previous
#include <cuda_runtime.h>

// Problem shapes
#define B_ 128
#define S_ 37
#define T_ 2048
#define D_ 256
#define ST_ 8
#define C_ 2
#define MERGED_ 264
#define NF (2*S_)          // 74 features (x ++ mask)
#define TC 128             // time chunk per CTA
#define NCHUNK (T_/TC)     // 16

// Per-chunk partial reductions (written without atomics -> deterministic)
__device__ float g_px[(size_t)NCHUNK * B_ * NF];
__device__ float g_pm[NCHUNK * B_];
__device__ float g_pt[NCHUNK * B_];

__device__ __forceinline__ float wred(float v) {
#pragma unroll
    for (int o = 16; o > 0; o >>= 1) v += __shfl_xor_sync(0xffffffffu, v, o);
    return v;
}

// ---------------------------------------------------------------------------
// Stage 1: HBM/L2-roofline pass over x + sensor_mask (77.6 MB).
// Mask staged as raw ints: the load loop is pure LDG->STS (no I2F on the
// load critical path); conversion happens in the consume phase.
// ---------------------------------------------------------------------------
__global__ __launch_bounds__(256) void stage1(const float* __restrict__ x,
                                              const int*   __restrict__ smk,
                                              const float* __restrict__ tm) {
    __shared__ float xs[S_ * TC];
    __shared__ int   msi[S_ * TC];
    __shared__ float valid[TC];
    __shared__ float red[8][2];

    const int chunk = blockIdx.x;
    const int b     = blockIdx.y;
    const int t0    = chunk * TC;

    const float* xb = x   + (size_t)b * S_ * T_ + t0;
    const int*   mb = smk + (size_t)b * S_ * T_ + t0;

    for (int idx = threadIdx.x; idx < S_ * (TC / 4); idx += 256) {
        int s = idx / (TC / 4);
        int j = (idx % (TC / 4)) * 4;
        float4 v = *(const float4*)(xb + (size_t)s * T_ + j);
        *(float4*)(xs + s * TC + j) = v;
        int4 m = *(const int4*)(mb + (size_t)s * T_ + j);
        *(int4*)(msi + s * TC + j) = m;
    }
    __syncthreads();

    float vf = 0.f, tv = 0.f;
    if (threadIdx.x < TC) {
        const int t = threadIdx.x;
        int nz = 0;
#pragma unroll
        for (int s = 0; s < S_; s++) {
            nz |= (xs[s * TC + t] != 0.f);
            nz |= (msi[s * TC + t] != 0);
        }
        vf = nz ? 1.f : 0.f;
        valid[t] = vf;
        tv = vf * tm[(size_t)b * T_ + t0 + t];
    }

    const int w = threadIdx.x >> 5, lane = threadIdx.x & 31;
    float rv = wred(vf), rt = wred(tv);
    if (lane == 0) { red[w][0] = rv; red[w][1] = rt; }
    __syncthreads();   // also makes valid[] visible to all warps
    if (threadIdx.x == 0) {
        float a = 0.f, c = 0.f;
#pragma unroll
        for (int i = 0; i < 8; i++) { a += red[i][0]; c += red[i][1]; }
        g_pm[chunk * B_ + b] = a;
        g_pt[chunk * B_ + b] = c;
    }

    for (int f = w; f < NF; f += 8) {
        float p = 0.f;
        if (f < S_) {
            const float* src = xs + f * TC;
#pragma unroll
            for (int j = lane; j < TC; j += 32) p += valid[j] * src[j];
        } else {
            const int* src = msi + (f - S_) * TC;
#pragma unroll
            for (int j = lane; j < TC; j += 32) p += valid[j] * (float)src[j];
        }
        p = wred(p);
        if (lane == 0) g_px[((size_t)chunk * B_ + b) * NF + f] = p;
    }
}

// ---------------------------------------------------------------------------
// Stage 2: fused per-batch MLP, 128 CTAs x 288 threads. All global-read
// loops use explicit register batches (w[16]) so ~16 loads are in flight
// per thread instead of ptxas's default ~4.
// ---------------------------------------------------------------------------
__global__ __launch_bounds__(288) void stage2(
    const float* __restrict__ stat,
    const float* __restrict__ Ws,  const float* __restrict__ bs,
    const float* __restrict__ Wt,  const float* __restrict__ bt,
    const float* __restrict__ Wst, const float* __restrict__ bst,
    const float* __restrict__ Wm,  const float* __restrict__ bm,
    const float* __restrict__ Wc,  const float* __restrict__ bc,
    float* __restrict__ out) {
    __shared__ float xsum[NF];
    __shared__ float comb[MERGED_];
    __shared__ float comb2[MERGED_];
    __shared__ float sden[2];

    const int b = blockIdx.x;
    const int tid = threadIdx.x;

    // Reduce per-chunk partials (16 independent loads, batched).
    if (tid < NF) {
        float v[NCHUNK];
#pragma unroll
        for (int c = 0; c < NCHUNK; c++)
            v[c] = g_px[((size_t)c * B_ + b) * NF + tid];
        float a = 0.f;
#pragma unroll
        for (int c = 0; c < NCHUNK; c++) a += v[c];
        xsum[tid] = a;
    }
    if (tid == 287) {
        float a = 0.f, t = 0.f;
#pragma unroll
        for (int c = 0; c < NCHUNK; c++) { a += g_pm[c * B_ + b]; t += g_pt[c * B_ + b]; }
        float den = fmaxf(a, 1e-9f);
        sden[0] = den;
        sden[1] = t / den;
    }
    __syncthreads();

    const float den = sden[0], tsc = sden[1];

    // pooled projection: K=74 = 4*16 + 10, register-batched column reads.
    if (tid < D_) {
        const float* Wcol = Ws + tid;
        float acc = 0.f;
#pragma unroll
        for (int k0 = 0; k0 < 64; k0 += 16) {
            float w[16];
#pragma unroll
            for (int u = 0; u < 16; u++) w[u] = Wcol[(size_t)(k0 + u) * D_];
            float a0 = 0.f, a1 = 0.f, a2 = 0.f, a3 = 0.f;
#pragma unroll
            for (int u = 0; u < 16; u += 4) {
                a0 += w[u]     * xsum[k0 + u];
                a1 += w[u + 1] * xsum[k0 + u + 1];
                a2 += w[u + 2] * xsum[k0 + u + 2];
                a3 += w[u + 3] * xsum[k0 + u + 3];
            }
            acc += (a0 + a1) + (a2 + a3);
        }
        {   // tail: k = 64..73
            float w[10];
#pragma unroll
            for (int u = 0; u < 10; u++) w[u] = Wcol[(size_t)(64 + u) * D_];
#pragma unroll
            for (int u = 0; u < 10; u++) acc += w[u] * xsum[64 + u];
        }
        comb[tid] = acc / den + bs[tid] + bt[tid] + tsc * Wt[tid];
    }
    // static embedding (8 dims) on the spare warp.
    if (tid >= 256 && tid < 256 + ST_) {
        const int j = tid - 256;
        float p = bst[j];
#pragma unroll
        for (int i = 0; i < ST_; i++) p += stat[b * ST_ + i] * Wst[i * ST_ + j];
        comb[D_ + j] = p;
    }
    __syncthreads();

    // merge: relu(comb @ Wm + bm). K=264 = 16*16 + 8, register-batched.
    if (tid < MERGED_) {
        const float* Wcol = Wm + tid;
        float acc = bm[tid];
#pragma unroll 2
        for (int k0 = 0; k0 < 256; k0 += 16) {
            float w[16];
#pragma unroll
            for (int u = 0; u < 16; u++) w[u] = Wcol[(size_t)(k0 + u) * MERGED_];
            float a0 = 0.f, a1 = 0.f, a2 = 0.f, a3 = 0.f;
#pragma unroll
            for (int u = 0; u < 16; u += 4) {
                a0 += w[u]     * comb[k0 + u];
                a1 += w[u + 1] * comb[k0 + u + 1];
                a2 += w[u + 2] * comb[k0 + u + 2];
                a3 += w[u + 3] * comb[k0 + u + 3];
            }
            acc += (a0 + a1) + (a2 + a3);
        }
        {   // tail: k = 256..263
            float w[8];
#pragma unroll
            for (int u = 0; u < 8; u++) w[u] = Wcol[(size_t)(256 + u) * MERGED_];
#pragma unroll
            for (int u = 0; u < 8; u++) acc += w[u] * comb[256 + u];
        }
        comb2[tid] = fmaxf(acc, 0.f);
    }
    __syncthreads();

    // classifier: warp 0 -> class 0, warp 1 -> class 1.
    const int w = tid >> 5, lane = tid & 31;
    if (w < C_) {
        float p = 0.f;
#pragma unroll
        for (int i = lane; i < MERGED_; i += 32) p += comb2[i] * Wc[i * C_ + w];
        p = wred(p);
        if (lane == 0) out[b * C_ + w] = p + bc[w];
    }
}

extern "C" void kernel_launch(void* const* d_in, const int* in_sizes, int n_in,
                              void* d_out, int out_size) {
    const float* x   = (const float*)d_in[0];
    const float* st  = (const float*)d_in[1];
    const float* tm  = (const float*)d_in[2];
    const int*   smk = (const int*)  d_in[3];
    const float* Ws  = (const float*)d_in[4];
    const float* bs  = (const float*)d_in[5];
    const float* Wt  = (const float*)d_in[6];
    const float* bt  = (const float*)d_in[7];
    const float* Wst = (const float*)d_in[8];
    const float* bst = (const float*)d_in[9];
    const float* Wm  = (const float*)d_in[10];
    const float* bm  = (const float*)d_in[11];
    const float* Wc  = (const float*)d_in[12];
    const float* bc  = (const float*)d_in[13];

    stage1<<<dim3(NCHUNK, B_), 256>>>(x, smk, tm);
    stage2<<<B_, 288>>>(st, Ws, bs, Wt, bt, Wst, bst, Wm, bm, Wc, bc,
                        (float*)d_out);
}